// round 8
// baseline (speedup 1.0000x reference)
#include <cuda_runtime.h>
#include <cuda_fp16.h>
#include <cstdint>

#define NMAX 100000
#define EMAX 1601000
#define HEADS 8
#define F 128
#define NEG_SLOPE 0.2f

// ---------------- static scratch (no allocation) ----------------
__device__ __align__(16) __half g_h[(size_t)NMAX * F];   // 25.6 MB (fp16)
__device__ __align__(16) float g_asrc[NMAX * HEADS];
__device__ __align__(16) float g_adst[NMAX * HEADS];
__device__ int g_cnt[NMAX];
__device__ int g_start[NMAX];
__device__ int g_cursor[NMAX];
__device__ int g_esrc[EMAX];
__device__ int g_bsum[128];
__device__ int g_idx64;

// ---------------- init: zero counts + parallel dtype sniff ----------------
__global__ void init_kernel(const long long* __restrict__ ei, long long E, int nodes) {
    int i = blockIdx.x * blockDim.x + threadIdx.x;
    if (i < nodes) g_cnt[i] = 0;
    if (blockIdx.x == 0 && threadIdx.x < 32) {
        long long stride = E / 32;
        if (stride < 1) stride = 1;
        long long v = ei[stride * threadIdx.x];
        unsigned bad = __ballot_sync(0xffffffffu, v < 0 || v >= NMAX);
        if (threadIdx.x == 0) g_idx64 = (bad == 0u);
    }
}

// ---------------- node transform: h = xW (fp16 out), attention scalars ----------------
__global__ void __launch_bounds__(128) node_kernel(
    const float* __restrict__ x, const float* __restrict__ W,
    const float* __restrict__ att_src, const float* __restrict__ att_dst,
    int nodes)
{
    __shared__ float sW[16 * F];
    __shared__ float sx[32][16];
    const int t = threadIdx.x;
    for (int i = t; i < 16 * F; i += 128) sW[i] = W[i];

    const int base = blockIdx.x * 32;
    const int nrem = min(32, nodes - base);
    if (t < (nrem * 16) / 4)
        ((float4*)&sx[0][0])[t] = ((const float4*)(x + (size_t)base * 16))[t];
    __syncthreads();

    const int head = t >> 4;
    const int c    = t & 15;
    const float as = att_src[t];
    const float ad = att_dst[t];

    for (int nn = 0; nn < nrem; nn++) {
        const int n = base + nn;
        float hj = 0.f;
        #pragma unroll
        for (int k = 0; k < 16; k++)
            hj = fmaf(sx[nn][k], sW[k * F + t], hj);

        float s1 = hj * as, s2 = hj * ad;
        #pragma unroll
        for (int off = 8; off; off >>= 1) {
            s1 += __shfl_xor_sync(0xffffffffu, s1, off, 16);
            s2 += __shfl_xor_sync(0xffffffffu, s2, off, 16);
        }
        float hn = __shfl_down_sync(0xffffffffu, hj, 1);
        if ((t & 1) == 0)
            *(__half2*)&g_h[(size_t)n * F + t] = __floats2half2_rn(hj, hn);
        if (c == 0) {
            g_asrc[n * HEADS + head] = s1;
            g_adst[n * HEADS + head] = s2;
        }
    }
}

// ---------------- CSR build ----------------
__global__ void hist_kernel(const long long* __restrict__ ei64,
                            const int* __restrict__ ei32, long long E) {
    const long long base = (long long)blockIdx.x * 1024 + threadIdx.x;
    const int use64 = g_idx64;
    #pragma unroll
    for (int i = 0; i < 4; i++) {
        long long e = base + i * 256;
        if (e < E) {
            int dst = use64 ? (int)ei64[E + e] : ei32[E + e];
            atomicAdd(&g_cnt[dst], 1);
        }
    }
}

__global__ void scanA_kernel(int nodes) {
    __shared__ int sh[256];
    int t = threadIdx.x, b = blockIdx.x;
    int base = (b * 256 + t) * 4;
    int s = 0;
    #pragma unroll
    for (int i = 0; i < 4; i++) { int j = base + i; if (j < nodes) s += g_cnt[j]; }
    sh[t] = s; __syncthreads();
    for (int off = 128; off; off >>= 1) {
        if (t < off) sh[t] += sh[t + off];
        __syncthreads();
    }
    if (t == 0) g_bsum[b] = sh[0];
}

// fused scanB+scanC: each block redundantly scans the 128 block sums
__global__ void scanC_kernel(int nodes) {
    __shared__ int sbs[128];
    __shared__ int sh[256];
    int t = threadIdx.x, b = blockIdx.x;
    if (t < 128) sbs[t] = g_bsum[t];
    __syncthreads();
    for (int off = 1; off < 128; off <<= 1) {
        int v = (t >= off && t < 128) ? sbs[t - off] : 0;
        __syncthreads();
        if (t < 128) sbs[t] += v;
        __syncthreads();
    }
    const int blockbase = (b > 0) ? sbs[b - 1] : 0;

    int base = (b * 256 + t) * 4;
    int c[4]; int s = 0;
    #pragma unroll
    for (int i = 0; i < 4; i++) {
        c[i] = (base + i < nodes) ? g_cnt[base + i] : 0;
        s += c[i];
    }
    sh[t] = s; __syncthreads();
    for (int off = 1; off < 256; off <<= 1) {
        int v = (t >= off) ? sh[t - off] : 0;
        __syncthreads();
        sh[t] += v;
        __syncthreads();
    }
    int run = blockbase + sh[t] - s;
    #pragma unroll
    for (int i = 0; i < 4; i++) {
        if (base + i < nodes) {
            g_start[base + i]  = run;
            g_cursor[base + i] = run;
            run += c[i];
        }
    }
}

__global__ void scatter_kernel(const long long* __restrict__ ei64,
                               const int* __restrict__ ei32, long long E) {
    const long long base = (long long)blockIdx.x * 512 + threadIdx.x;
    const int use64 = g_idx64;
    #pragma unroll
    for (int i = 0; i < 2; i++) {
        long long e = base + i * 256;
        if (e < E) {
            int src, dst;
            if (use64) { src = (int)ei64[e]; dst = (int)ei64[E + e]; }
            else       { src = ei32[e];      dst = ei32[E + e]; }
            int pos = atomicAdd(&g_cursor[dst], 1);
            g_esrc[pos] = src;
        }
    }
}

// ---------------- gather + finalize fused (1 warp / node, half-warp / edge) ---------
// lane = g*16 + sl; group g processes virtual edge 2*it+g; lane owns 8 features
// [sl*8, sl*8+8) (head hh = sl>>1). Virtual edge 0 = self loop, rest = CSR edges.
__global__ void __launch_bounds__(256) gather_kernel(
    const float* __restrict__ bias, const float* __restrict__ fc_w,
    const float* __restrict__ fc_b, float* __restrict__ out, int nodes)
{
    __shared__ float sb[F];
    __shared__ float sw[5][F];
    __shared__ float sfb[5];
    const int t = threadIdx.x;
    for (int i = t; i < F; i += 256) sb[i] = bias[i];
    for (int i = t; i < 5 * F; i += 256) { int j = i / 5, k = i % 5; sw[k][j] = fc_w[i]; }
    if (t < 5) sfb[t] = fc_b[t];
    __syncthreads();

    const int n = blockIdx.x * 8 + (t >> 5);
    if (n >= nodes) return;
    const int lane = t & 31;
    const int g  = lane >> 4;      // edge-partition group
    const int sl = lane & 15;      // sub-lane: feature block
    const int hh = sl >> 1;        // head for this lane's features
    const int j0 = sl * 8;         // first feature owned by this lane

    const float adw = g_adst[n * HEADS + hh];
    const int s0 = g_start[n];
    const int total = g_cnt[n] + 1;   // + self loop

    float dsum = 0.f;
    float ac[8];
    #pragma unroll
    for (int k = 0; k < 8; k++) ac[k] = 0.f;

    for (int it = 0; 2 * it < total; it++) {
        const int ve = 2 * it + g;
        const bool valid = (ve < total);
        int idx = n;
        if (ve > 0 && valid) idx = __ldg(&g_esrc[s0 + ve - 1]);

        float a = __ldg(&g_asrc[idx * HEADS + hh]) + adw;
        a = fmaxf(a, NEG_SLOPE * a);
        const float w = valid ? __expf(a) : 0.f;

        const uint4 r = *(const uint4*)&g_h[(size_t)idx * F + j0];
        const float2 f0 = __half22float2(*(const __half2*)&r.x);
        const float2 f1 = __half22float2(*(const __half2*)&r.y);
        const float2 f2 = __half22float2(*(const __half2*)&r.z);
        const float2 f3 = __half22float2(*(const __half2*)&r.w);

        dsum += w;
        ac[0] = fmaf(w, f0.x, ac[0]); ac[1] = fmaf(w, f0.y, ac[1]);
        ac[2] = fmaf(w, f1.x, ac[2]); ac[3] = fmaf(w, f1.y, ac[3]);
        ac[4] = fmaf(w, f2.x, ac[4]); ac[5] = fmaf(w, f2.y, ac[5]);
        ac[6] = fmaf(w, f3.x, ac[6]); ac[7] = fmaf(w, f3.y, ac[7]);
    }

    // merge the two edge-partitions (lane <-> lane^16)
    dsum += __shfl_xor_sync(0xffffffffu, dsum, 16);
    #pragma unroll
    for (int k = 0; k < 8; k++)
        ac[k] += __shfl_xor_sync(0xffffffffu, ac[k], 16);

    const float inv = 1.f / (dsum + 1e-16f);
    float o[8];
    #pragma unroll
    for (int k = 0; k < 8; k++)
        o[k] = fmaxf(fmaf(ac[k], inv, sb[j0 + k]), 0.f);

    float p[5];
    #pragma unroll
    for (int k = 0; k < 5; k++) {
        float s = 0.f;
        #pragma unroll
        for (int j = 0; j < 8; j++)
            s = fmaf(o[j], sw[k][j0 + j], s);
        p[k] = s;
    }
    // reduce across the 16 sub-lanes (both halves hold identical data)
    #pragma unroll
    for (int off = 8; off; off >>= 1) {
        #pragma unroll
        for (int k = 0; k < 5; k++)
            p[k] += __shfl_xor_sync(0xffffffffu, p[k], off, 16);
    }
    if (lane == 0) {
        #pragma unroll
        for (int k = 0; k < 5; k++) p[k] += sfb[k];
        float m = p[0];
        #pragma unroll
        for (int k = 1; k < 5; k++) m = fmaxf(m, p[k]);
        float s = 0.f;
        #pragma unroll
        for (int k = 0; k < 5; k++) s += __expf(p[k] - m);
        const float lse = m + logf(s);
        #pragma unroll
        for (int k = 0; k < 5; k++)
            out[(size_t)n * 5 + k] = p[k] - lse;
    }
}

// ---------------- launch ----------------
extern "C" void kernel_launch(void* const* d_in, const int* in_sizes, int n_in,
                              void* d_out, int out_size)
{
    const float* x       = (const float*)d_in[0];
    const void*  ei      = d_in[1];
    const float* W       = (const float*)d_in[2];
    const float* att_src = (const float*)d_in[3];
    const float* att_dst = (const float*)d_in[4];
    const float* bias    = (const float*)d_in[5];
    const float* fc_w    = (const float*)d_in[6];
    const float* fc_b    = (const float*)d_in[7];
    float* out = (float*)d_out;

    const int nodes = in_sizes[0] / 16;
    const long long E = (long long)in_sizes[1] / 2;

    init_kernel<<<(nodes + 255) / 256, 256>>>((const long long*)ei, E, nodes);
    node_kernel<<<(nodes + 31) / 32, 128>>>(x, W, att_src, att_dst, nodes);

    hist_kernel<<<(int)((E + 1023) / 1024), 256>>>((const long long*)ei, (const int*)ei, E);
    scanA_kernel<<<128, 256>>>(nodes);
    scanC_kernel<<<128, 256>>>(nodes);
    scatter_kernel<<<(int)((E + 511) / 512), 256>>>((const long long*)ei, (const int*)ei, E);

    gather_kernel<<<(nodes + 7) / 8, 256>>>(bias, fc_w, fc_b, out, nodes);
}

// round 10
// speedup vs baseline: 1.0373x; 1.0373x over previous
#include <cuda_runtime.h>
#include <cuda_fp16.h>
#include <cstdint>

#define NMAX 100000
#define EMAX 1601000
#define HEADS 8
#define F 128
#define NEG_SLOPE 0.2f

// ---------------- static scratch (no allocation) ----------------
__device__ __align__(16) __half g_h[(size_t)NMAX * F];   // 25.6 MB (fp16)
__device__ __align__(16) float g_asrc[NMAX * HEADS];
__device__ __align__(16) float g_adst[NMAX * HEADS];
__device__ int g_cnt[NMAX];
__device__ int g_start[NMAX];
__device__ int g_cursor[NMAX];
__device__ int g_esrc[EMAX];
__device__ int g_bsum[256];
__device__ int g_idx64;
__device__ int g_bar0, g_bar1;

// ---------------- node transform + init (h = xW fp16, attention scalars) ----------
__global__ void __launch_bounds__(128) node_kernel(
    const float* __restrict__ x, const float* __restrict__ W,
    const float* __restrict__ att_src, const float* __restrict__ att_dst,
    const long long* __restrict__ ei, long long E, int nodes)
{
    // init duties: zero cnt, zero barrier counters, dtype sniff
    const int gid = blockIdx.x * 128 + threadIdx.x;
    if (gid < nodes) g_cnt[gid] = 0;
    if (blockIdx.x == 0) {
        if (threadIdx.x == 0) { g_bar0 = 0; g_bar1 = 0; }
        if (threadIdx.x < 32) {
            long long stride = E / 32;
            if (stride < 1) stride = 1;
            long long v = ei[stride * threadIdx.x];
            unsigned bad = __ballot_sync(0xffffffffu, v < 0 || v >= NMAX);
            if (threadIdx.x == 0) g_idx64 = (bad == 0u);
        }
    }

    __shared__ float sW[16 * F];
    __shared__ float sx[32][16];
    const int t = threadIdx.x;
    for (int i = t; i < 16 * F; i += 128) sW[i] = W[i];

    const int base = blockIdx.x * 32;
    const int nrem = min(32, nodes - base);
    if (nrem <= 0) return;
    if (t < (nrem * 16) / 4)
        ((float4*)&sx[0][0])[t] = ((const float4*)(x + (size_t)base * 16))[t];
    __syncthreads();

    const int head = t >> 4;
    const int c    = t & 15;
    const float as = att_src[t];
    const float ad = att_dst[t];

    for (int nn = 0; nn < nrem; nn++) {
        const int n = base + nn;
        float hj = 0.f;
        #pragma unroll
        for (int k = 0; k < 16; k++)
            hj = fmaf(sx[nn][k], sW[k * F + t], hj);

        float s1 = hj * as, s2 = hj * ad;
        #pragma unroll
        for (int off = 8; off; off >>= 1) {
            s1 += __shfl_xor_sync(0xffffffffu, s1, off, 16);
            s2 += __shfl_xor_sync(0xffffffffu, s2, off, 16);
        }
        float hn = __shfl_down_sync(0xffffffffu, hj, 1);
        if ((t & 1) == 0)
            *(__half2*)&g_h[(size_t)n * F + t] = __floats2half2_rn(hj, hn);
        if (c == 0) {
            g_asrc[n * HEADS + head] = s1;
            g_adst[n * HEADS + head] = s2;
        }
    }
}

// ---------------- histogram ----------------
__global__ void hist_kernel(const long long* __restrict__ ei64,
                            const int* __restrict__ ei32, long long E) {
    const long long base = (long long)blockIdx.x * 1024 + threadIdx.x;
    const int use64 = g_idx64;
    #pragma unroll
    for (int i = 0; i < 4; i++) {
        long long e = base + i * 256;
        if (e < E) {
            int dst = use64 ? (int)ei64[E + e] : ei32[E + e];
            atomicAdd(&g_cnt[dst], 1);
        }
    }
}

// ---------------- fused scan + scatter (persistent 256x512, all resident) --------
__device__ __forceinline__ void grid_bar(int* ctr, int expected) {
    __syncthreads();
    __threadfence();
    if (threadIdx.x == 0) {
        atomicAdd(ctr, 1);
        while (*(volatile int*)ctr < expected) { }
    }
    __syncthreads();
}

__global__ void __launch_bounds__(512) csr_kernel(
    const long long* __restrict__ ei64, const int* __restrict__ ei32,
    long long E, int nodes)
{
    __shared__ int sh[512];
    __shared__ int sbs[256];
    const int t = threadIdx.x, b = blockIdx.x;
    const int i = b * 512 + t;

    // block-local inclusive scan of counts
    const int c = (i < nodes) ? g_cnt[i] : 0;
    sh[t] = c; __syncthreads();
    for (int off = 1; off < 512; off <<= 1) {
        int v = (t >= off) ? sh[t - off] : 0;
        __syncthreads();
        sh[t] += v;
        __syncthreads();
    }
    if (t == 511) g_bsum[b] = sh[511];
    const int excl = sh[t] - c;

    grid_bar(&g_bar0, 256);   // all block sums visible

    if (t < 256) sbs[t] = g_bsum[t];
    __syncthreads();
    for (int off = 1; off < 256; off <<= 1) {
        int v = (t >= off && t < 256) ? sbs[t - off] : 0;
        __syncthreads();
        if (t < 256) sbs[t] += v;
        __syncthreads();
    }
    const int blockbase = (b > 0) ? sbs[b - 1] : 0;
    if (i < nodes) {
        g_start[i]  = blockbase + excl;
        g_cursor[i] = blockbase + excl;
    }

    grid_bar(&g_bar1, 256);   // all cursors visible

    // scatter, grid-strided
    const int use64 = g_idx64;
    const long long NT = 256LL * 512;
    for (long long e = (long long)b * 512 + t; e < E; e += NT) {
        int src, dst;
        if (use64) { src = (int)ei64[e]; dst = (int)ei64[E + e]; }
        else       { src = ei32[e];      dst = ei32[E + e]; }
        int pos = atomicAdd(&g_cursor[dst], 1);
        g_esrc[pos] = src;
    }
}

// ---------------- gather + finalize fused (1 warp / node) — best (R4) variant ----
__device__ __forceinline__ void acc_edge(int idx, int h, int j0, float adw,
                                         float& dsum, float& ax, float& ay,
                                         float& az, float& aw)
{
    float a = g_asrc[idx * HEADS + h] + adw;
    a = fmaxf(a, NEG_SLOPE * a);
    const float w = __expf(a);
    uint2 r = *(const uint2*)&g_h[(size_t)idx * F + j0];
    float2 lo = __half22float2(*(__half2*)&r.x);
    float2 hi = __half22float2(*(__half2*)&r.y);
    dsum += w;
    ax = fmaf(w, lo.x, ax); ay = fmaf(w, lo.y, ay);
    az = fmaf(w, hi.x, az); aw = fmaf(w, hi.y, aw);
}

__global__ void __launch_bounds__(256) gather_kernel(
    const float* __restrict__ bias, const float* __restrict__ fc_w,
    const float* __restrict__ fc_b, float* __restrict__ out, int nodes)
{
    __shared__ float sb[F];
    __shared__ float sw[5][F];
    __shared__ float sfb[5];
    const int t = threadIdx.x;
    for (int i = t; i < F; i += 256) sb[i] = bias[i];
    for (int i = t; i < 5 * F; i += 256) { int j = i / 5, k = i % 5; sw[k][j] = fc_w[i]; }
    if (t < 5) sfb[t] = fc_b[t];
    __syncthreads();

    const int n = blockIdx.x * 8 + (t >> 5);
    if (n >= nodes) return;
    const int lane = t & 31;
    const int h = lane >> 2;
    const int j0 = lane * 4;

    const float adw = g_adst[n * HEADS + h];

    float dsum = 0.f, ax = 0.f, ay = 0.f, az = 0.f, aw = 0.f;
    acc_edge(n, h, j0, adw, dsum, ax, ay, az, aw);   // self loop

    const int s0 = g_start[n];
    const int end = s0 + g_cnt[n];
    int e = s0;
    for (; e + 4 <= end; e += 4) {
        int i0 = g_esrc[e], i1 = g_esrc[e + 1], i2 = g_esrc[e + 2], i3 = g_esrc[e + 3];
        float a0 = g_asrc[i0 * HEADS + h] + adw;
        float a1 = g_asrc[i1 * HEADS + h] + adw;
        float a2 = g_asrc[i2 * HEADS + h] + adw;
        float a3 = g_asrc[i3 * HEADS + h] + adw;
        uint2 r0 = *(const uint2*)&g_h[(size_t)i0 * F + j0];
        uint2 r1 = *(const uint2*)&g_h[(size_t)i1 * F + j0];
        uint2 r2 = *(const uint2*)&g_h[(size_t)i2 * F + j0];
        uint2 r3 = *(const uint2*)&g_h[(size_t)i3 * F + j0];
        a0 = fmaxf(a0, NEG_SLOPE * a0); float w0 = __expf(a0);
        a1 = fmaxf(a1, NEG_SLOPE * a1); float w1 = __expf(a1);
        a2 = fmaxf(a2, NEG_SLOPE * a2); float w2 = __expf(a2);
        a3 = fmaxf(a3, NEG_SLOPE * a3); float w3 = __expf(a3);
        dsum += (w0 + w1) + (w2 + w3);
        float2 l0 = __half22float2(*(__half2*)&r0.x), u0 = __half22float2(*(__half2*)&r0.y);
        float2 l1 = __half22float2(*(__half2*)&r1.x), u1 = __half22float2(*(__half2*)&r1.y);
        float2 l2 = __half22float2(*(__half2*)&r2.x), u2 = __half22float2(*(__half2*)&r2.y);
        float2 l3 = __half22float2(*(__half2*)&r3.x), u3 = __half22float2(*(__half2*)&r3.y);
        ax += w0 * l0.x + w1 * l1.x + w2 * l2.x + w3 * l3.x;
        ay += w0 * l0.y + w1 * l1.y + w2 * l2.y + w3 * l3.y;
        az += w0 * u0.x + w1 * u1.x + w2 * u2.x + w3 * u3.x;
        aw += w0 * u0.y + w1 * u1.y + w2 * u2.y + w3 * u3.y;
    }
    for (; e < end; e++)
        acc_edge(g_esrc[e], h, j0, adw, dsum, ax, ay, az, aw);

    const float inv = 1.f / (dsum + 1e-16f);
    float o0 = fmaxf(fmaf(ax, inv, sb[j0 + 0]), 0.f);
    float o1 = fmaxf(fmaf(ay, inv, sb[j0 + 1]), 0.f);
    float o2 = fmaxf(fmaf(az, inv, sb[j0 + 2]), 0.f);
    float o3 = fmaxf(fmaf(aw, inv, sb[j0 + 3]), 0.f);

    float p[5];
    #pragma unroll
    for (int k = 0; k < 5; k++) {
        p[k] = o0 * sw[k][j0 + 0] + o1 * sw[k][j0 + 1]
             + o2 * sw[k][j0 + 2] + o3 * sw[k][j0 + 3];
    }
    #pragma unroll
    for (int off = 16; off; off >>= 1) {
        #pragma unroll
        for (int k = 0; k < 5; k++)
            p[k] += __shfl_xor_sync(0xffffffffu, p[k], off);
    }
    if (lane == 0) {
        #pragma unroll
        for (int k = 0; k < 5; k++) p[k] += sfb[k];
        float m = p[0];
        #pragma unroll
        for (int k = 1; k < 5; k++) m = fmaxf(m, p[k]);
        float s = 0.f;
        #pragma unroll
        for (int k = 0; k < 5; k++) s += __expf(p[k] - m);
        const float lse = m + logf(s);
        #pragma unroll
        for (int k = 0; k < 5; k++)
            out[(size_t)n * 5 + k] = p[k] - lse;
    }
}

// ---------------- launch ----------------
extern "C" void kernel_launch(void* const* d_in, const int* in_sizes, int n_in,
                              void* d_out, int out_size)
{
    const float* x       = (const float*)d_in[0];
    const void*  ei      = d_in[1];
    const float* W       = (const float*)d_in[2];
    const float* att_src = (const float*)d_in[3];
    const float* att_dst = (const float*)d_in[4];
    const float* bias    = (const float*)d_in[5];
    const float* fc_w    = (const float*)d_in[6];
    const float* fc_b    = (const float*)d_in[7];
    float* out = (float*)d_out;

    const int nodes = in_sizes[0] / 16;
    const long long E = (long long)in_sizes[1] / 2;

    node_kernel<<<(nodes + 31) / 32, 128>>>(x, W, att_src, att_dst,
                                            (const long long*)ei, E, nodes);
    hist_kernel<<<(int)((E + 1023) / 1024), 256>>>((const long long*)ei, (const int*)ei, E);
    csr_kernel<<<256, 512>>>((const long long*)ei, (const int*)ei, E, nodes);
    gather_kernel<<<(nodes + 7) / 8, 256>>>(bias, fc_w, fc_b, out, nodes);
}

// round 12
// speedup vs baseline: 1.0502x; 1.0124x over previous
#include <cuda_runtime.h>
#include <cuda_fp16.h>
#include <cstdint>

#define NMAX 100000
#define EMAX 2000000
#define HEADS 8
#define F 128
#define NEG_SLOPE 0.2f
#define LOG2E 1.4426950408889634f

// ---------------- static scratch (no allocation) ----------------
// +1 row: sentinel node NMAX (asrc = -1e30 -> weight exactly 0, h row = 0)
__device__ __align__(16) __half g_h[(size_t)(NMAX + 1) * F];
__device__ __align__(16) float g_asrc[(NMAX + 1) * HEADS];
__device__ __align__(16) float g_adst[NMAX * HEADS];
__device__ int g_cnt[NMAX];
__device__ int g_start[NMAX];
__device__ int g_cursor[NMAX];
__device__ __align__(16) int g_esrc[EMAX];
__device__ int g_bsum[256];
__device__ int g_idx64;
__device__ int g_bar0, g_bar1;

__device__ __forceinline__ float ex2f(float x) {
    float y; asm("ex2.approx.f32 %0, %1;" : "=f"(y) : "f"(x)); return y;
}

// ---------------- node transform + init ----------------
__global__ void __launch_bounds__(128) node_kernel(
    const float* __restrict__ x, const float* __restrict__ W,
    const float* __restrict__ att_src, const float* __restrict__ att_dst,
    const long long* __restrict__ ei, long long E, int nodes)
{
    const int gid = blockIdx.x * 128 + threadIdx.x;
    if (gid < nodes) g_cnt[gid] = 0;
    if (blockIdx.x == 0) {
        if (threadIdx.x == 0) { g_bar0 = 0; g_bar1 = 0; }
        if (threadIdx.x < 8)  g_asrc[NMAX * HEADS + threadIdx.x] = -1e30f;
        if (threadIdx.x < 64) ((uint32_t*)(g_h + (size_t)NMAX * F))[threadIdx.x] = 0u;
        if (threadIdx.x < 32) {
            long long stride = E / 32;
            if (stride < 1) stride = 1;
            long long v = ei[stride * threadIdx.x];
            unsigned bad = __ballot_sync(0xffffffffu, v < 0 || v >= NMAX);
            if (threadIdx.x == 0) g_idx64 = (bad == 0u);
        }
    }

    __shared__ float sW[16 * F];
    __shared__ float sx[32][16];
    const int t = threadIdx.x;
    for (int i = t; i < 16 * F; i += 128) sW[i] = W[i];

    const int base = blockIdx.x * 32;
    const int nrem = min(32, nodes - base);
    if (nrem <= 0) return;
    if (t < (nrem * 16) / 4)
        ((float4*)&sx[0][0])[t] = ((const float4*)(x + (size_t)base * 16))[t];
    __syncthreads();

    const int head = t >> 4;
    const int c    = t & 15;
    const float as = att_src[t];
    const float ad = att_dst[t];

    for (int nn = 0; nn < nrem; nn++) {
        const int n = base + nn;
        float hj = 0.f;
        #pragma unroll
        for (int k = 0; k < 16; k++)
            hj = fmaf(sx[nn][k], sW[k * F + t], hj);

        float s1 = hj * as, s2 = hj * ad;
        #pragma unroll
        for (int off = 8; off; off >>= 1) {
            s1 += __shfl_xor_sync(0xffffffffu, s1, off, 16);
            s2 += __shfl_xor_sync(0xffffffffu, s2, off, 16);
        }
        float hn = __shfl_down_sync(0xffffffffu, hj, 1);
        if ((t & 1) == 0)
            *(__half2*)&g_h[(size_t)n * F + t] = __floats2half2_rn(hj, hn);
        if (c == 0) {
            // pre-scaled by log2e: exp(lrelu(a)) == exp2(lrelu(a*log2e))
            g_asrc[n * HEADS + head] = s1 * LOG2E;
            g_adst[n * HEADS + head] = s2 * LOG2E;
        }
    }
}

// ---------------- histogram ----------------
__global__ void hist_kernel(const long long* __restrict__ ei64,
                            const int* __restrict__ ei32, long long E) {
    const long long base = (long long)blockIdx.x * 1024 + threadIdx.x;
    const int use64 = g_idx64;
    #pragma unroll
    for (int i = 0; i < 4; i++) {
        long long e = base + i * 256;
        if (e < E) {
            int dst = use64 ? (int)ei64[E + e] : ei32[E + e];
            atomicAdd(&g_cnt[dst], 1);
        }
    }
}

// ---------------- fused scan (padded) + padding-fill + scatter ----------------
__device__ __forceinline__ void grid_bar(int* ctr, int expected) {
    __syncthreads();
    __threadfence();
    if (threadIdx.x == 0) {
        atomicAdd(ctr, 1);
        while (*(volatile int*)ctr < expected) { }
    }
    __syncthreads();
}

__global__ void __launch_bounds__(512) csr_kernel(
    const long long* __restrict__ ei64, const int* __restrict__ ei32,
    long long E, int nodes)
{
    __shared__ int sh[512];
    __shared__ int sbs[256];
    const int t = threadIdx.x, b = blockIdx.x;
    const int i = b * 512 + t;

    const int cnt = (i < nodes) ? g_cnt[i] : 0;
    const int c = (cnt + 3) & ~3;          // padded count (4-aligned segments)
    sh[t] = c; __syncthreads();
    for (int off = 1; off < 512; off <<= 1) {
        int v = (t >= off) ? sh[t - off] : 0;
        __syncthreads();
        sh[t] += v;
        __syncthreads();
    }
    if (t == 511) g_bsum[b] = sh[511];
    const int excl = sh[t] - c;

    grid_bar(&g_bar0, 256);

    if (t < 256) sbs[t] = g_bsum[t];
    __syncthreads();
    for (int off = 1; off < 256; off <<= 1) {
        int v = (t >= off && t < 256) ? sbs[t - off] : 0;
        __syncthreads();
        if (t < 256) sbs[t] += v;
        __syncthreads();
    }
    const int blockbase = (b > 0) ? sbs[b - 1] : 0;
    if (i < nodes) {
        const int s = blockbase + excl;
        g_start[i]  = s;
        g_cursor[i] = s;
        // fill padding slots with sentinel (weight-0) entries
        for (int k = cnt; k < c; k++) g_esrc[s + k] = NMAX;
    }

    grid_bar(&g_bar1, 256);

    const int use64 = g_idx64;
    const long long NT = 256LL * 512;
    for (long long e = (long long)b * 512 + t; e < E; e += NT) {
        int src, dst;
        if (use64) { src = (int)ei64[e]; dst = (int)ei64[E + e]; }
        else       { src = ei32[e];      dst = ei32[E + e]; }
        int pos = atomicAdd(&g_cursor[dst], 1);
        g_esrc[pos] = src;
    }
}

// ---------------- gather + finalize (1 warp/node, branchless 4-edge groups) ------
__global__ void __launch_bounds__(256) gather_kernel(
    const float* __restrict__ bias, const float* __restrict__ fc_w,
    const float* __restrict__ fc_b, float* __restrict__ out, int nodes)
{
    __shared__ float sb[F];
    __shared__ float sw[5][F];
    __shared__ float sfb[5];
    const int t = threadIdx.x;
    for (int i = t; i < F; i += 256) sb[i] = bias[i];
    for (int i = t; i < 5 * F; i += 256) { int j = i / 5, k = i % 5; sw[k][j] = fc_w[i]; }
    if (t < 5) sfb[t] = fc_b[t];
    __syncthreads();

    const int n = blockIdx.x * 8 + (t >> 5);
    if (n >= nodes) return;
    const int lane = t & 31;
    const int h = lane >> 2;
    const int j0 = lane * 4;

    const float adw = g_adst[n * HEADS + h];

    // self loop
    float a = g_asrc[n * HEADS + h] + adw;
    a = fmaxf(a, NEG_SLOPE * a);
    float w = ex2f(a);
    uint2 r = *(const uint2*)&g_h[(size_t)n * F + j0];
    float2 lo = __half22float2(*(__half2*)&r.x);
    float2 hi = __half22float2(*(__half2*)&r.y);
    float dsum = w;
    float ax = w * lo.x, ay = w * lo.y, az = w * hi.x, aw = w * hi.y;

    const int s0 = g_start[n];
    const int groups = (g_cnt[n] + 3) >> 2;

    for (int g = 0; g < groups; g++) {
        const int4 iv = *(const int4*)&g_esrc[s0 + g * 4];
        float a0 = g_asrc[iv.x * HEADS + h] + adw;
        float a1 = g_asrc[iv.y * HEADS + h] + adw;
        float a2 = g_asrc[iv.z * HEADS + h] + adw;
        float a3 = g_asrc[iv.w * HEADS + h] + adw;
        uint2 r0 = *(const uint2*)&g_h[(size_t)iv.x * F + j0];
        uint2 r1 = *(const uint2*)&g_h[(size_t)iv.y * F + j0];
        uint2 r2 = *(const uint2*)&g_h[(size_t)iv.z * F + j0];
        uint2 r3 = *(const uint2*)&g_h[(size_t)iv.w * F + j0];
        a0 = fmaxf(a0, NEG_SLOPE * a0); float w0 = ex2f(a0);
        a1 = fmaxf(a1, NEG_SLOPE * a1); float w1 = ex2f(a1);
        a2 = fmaxf(a2, NEG_SLOPE * a2); float w2 = ex2f(a2);
        a3 = fmaxf(a3, NEG_SLOPE * a3); float w3 = ex2f(a3);
        dsum += (w0 + w1) + (w2 + w3);
        float2 l0 = __half22float2(*(__half2*)&r0.x), u0 = __half22float2(*(__half2*)&r0.y);
        float2 l1 = __half22float2(*(__half2*)&r1.x), u1 = __half22float2(*(__half2*)&r1.y);
        float2 l2 = __half22float2(*(__half2*)&r2.x), u2 = __half22float2(*(__half2*)&r2.y);
        float2 l3 = __half22float2(*(__half2*)&r3.x), u3 = __half22float2(*(__half2*)&r3.y);
        ax += w0 * l0.x + w1 * l1.x + w2 * l2.x + w3 * l3.x;
        ay += w0 * l0.y + w1 * l1.y + w2 * l2.y + w3 * l3.y;
        az += w0 * u0.x + w1 * u1.x + w2 * u2.x + w3 * u3.x;
        aw += w0 * u0.y + w1 * u1.y + w2 * u2.y + w3 * u3.y;
    }

    const float inv = 1.f / (dsum + 1e-16f);
    float o0 = fmaxf(fmaf(ax, inv, sb[j0 + 0]), 0.f);
    float o1 = fmaxf(fmaf(ay, inv, sb[j0 + 1]), 0.f);
    float o2 = fmaxf(fmaf(az, inv, sb[j0 + 2]), 0.f);
    float o3 = fmaxf(fmaf(aw, inv, sb[j0 + 3]), 0.f);

    float p[5];
    #pragma unroll
    for (int k = 0; k < 5; k++) {
        p[k] = o0 * sw[k][j0 + 0] + o1 * sw[k][j0 + 1]
             + o2 * sw[k][j0 + 2] + o3 * sw[k][j0 + 3];
    }
    #pragma unroll
    for (int off = 16; off; off >>= 1) {
        #pragma unroll
        for (int k = 0; k < 5; k++)
            p[k] += __shfl_xor_sync(0xffffffffu, p[k], off);
    }
    if (lane == 0) {
        #pragma unroll
        for (int k = 0; k < 5; k++) p[k] += sfb[k];
        float m = p[0];
        #pragma unroll
        for (int k = 1; k < 5; k++) m = fmaxf(m, p[k]);
        float s = 0.f;
        #pragma unroll
        for (int k = 0; k < 5; k++) s += __expf(p[k] - m);
        const float lse = m + logf(s);
        #pragma unroll
        for (int k = 0; k < 5; k++)
            out[(size_t)n * 5 + k] = p[k] - lse;
    }
}

// ---------------- launch ----------------
extern "C" void kernel_launch(void* const* d_in, const int* in_sizes, int n_in,
                              void* d_out, int out_size)
{
    const float* x       = (const float*)d_in[0];
    const void*  ei      = d_in[1];
    const float* W       = (const float*)d_in[2];
    const float* att_src = (const float*)d_in[3];
    const float* att_dst = (const float*)d_in[4];
    const float* bias    = (const float*)d_in[5];
    const float* fc_w    = (const float*)d_in[6];
    const float* fc_b    = (const float*)d_in[7];
    float* out = (float*)d_out;

    const int nodes = in_sizes[0] / 16;
    const long long E = (long long)in_sizes[1] / 2;

    node_kernel<<<(nodes + 31) / 32, 128>>>(x, W, att_src, att_dst,
                                            (const long long*)ei, E, nodes);
    hist_kernel<<<(int)((E + 1023) / 1024), 256>>>((const long long*)ei, (const int*)ei, E);
    csr_kernel<<<256, 512>>>((const long long*)ei, (const int*)ei, E, nodes);
    gather_kernel<<<(nodes + 7) / 8, 256>>>(bias, fc_w, fc_b, out, nodes);
}